// round 16
// baseline (speedup 1.0000x reference)
#include <cuda_runtime.h>
#include <cuda_fp16.h>
#include <cstdint>

#define B_  256
#define N_  32768
#define D_  1024
#define H_  16
#define DH_ 64

// ---------------- scratch ----------------
__device__ __align__(16) __half g_wq16[(size_t)D_ * D_];
__device__ __align__(16) __half g_wk16[(size_t)D_ * D_];
__device__ __align__(16) __half g_wv16[(size_t)D_ * D_];
__device__ __align__(16) __half g_qh16[(size_t)B_ * D_];
__device__ __align__(16) __half g_kh16[(size_t)N_ * D_];
__device__ __align__(16) __half g_vh16[(size_t)N_ * D_];
#define NSPLIT 32
__device__ __align__(16) float g_opart[(size_t)H_ * 4 * NSPLIT * 64 * DH_];
__device__ __align__(16) float g_dpart[(size_t)H_ * 4 * NSPLIT * 64];

// ======================= helpers =======================
__device__ __forceinline__ uint32_t smem_to_u32(const void* p) {
    uint32_t a;
    asm("{ .reg .u64 t; cvta.to.shared.u64 t, %1; cvt.u32.u64 %0, t; }" : "=r"(a) : "l"(p));
    return a;
}
__device__ __forceinline__ void cp16(uint32_t s, const void* g) {
    asm volatile("cp.async.cg.shared.global [%0], [%1], 16;" :: "r"(s), "l"(g) : "memory");
}
#define CP_COMMIT() asm volatile("cp.async.commit_group;" ::: "memory")
#define CP_WAIT(n)  asm volatile("cp.async.wait_group %0;" :: "n"(n) : "memory")

#define LDSM4(r, a) \
    asm volatile("ldmatrix.sync.aligned.m8n8.x4.shared.b16 {%0,%1,%2,%3}, [%4];" \
        : "=r"((r)[0]), "=r"((r)[1]), "=r"((r)[2]), "=r"((r)[3]) : "r"(a))
#define LDSM4T(r, a) \
    asm volatile("ldmatrix.sync.aligned.m8n8.x4.trans.shared.b16 {%0,%1,%2,%3}, [%4];" \
        : "=r"((r)[0]), "=r"((r)[1]), "=r"((r)[2]), "=r"((r)[3]) : "r"(a))

#define MMAF16(c, a, b0, b1) \
    asm volatile("mma.sync.aligned.m16n8k16.row.col.f32.f16.f16.f32 " \
        "{%0,%1,%2,%3}, {%4,%5,%6,%7}, {%8,%9}, {%0,%1,%2,%3};" \
        : "+f"((c)[0]), "+f"((c)[1]), "+f"((c)[2]), "+f"((c)[3]) \
        : "r"((a)[0]), "r"((a)[1]), "r"((a)[2]), "r"((a)[3]), "r"(b0), "r"(b1))

__device__ __forceinline__ uint32_t h2u(__half2 h) { return *reinterpret_cast<uint32_t*>(&h); }

// ======================= W-only fp32 -> fp16 convert (12 MB) =======================
#define WCHUNKS 131072u   // per W matrix: 1M elems / 8
__global__ __launch_bounds__(256) void cvt_w(
    const float4* __restrict__ wq, const float4* __restrict__ wk, const float4* __restrict__ wv,
    uint4* __restrict__ owq, uint4* __restrict__ owk, uint4* __restrict__ owv)
{
    uint32_t i = blockIdx.x * 256 + threadIdx.x;   // 0 .. 3*WCHUNKS-1
    const float4* s; uint4* d; uint32_t off;
    if      (i < WCHUNKS)     { s = wq; d = owq; off = i; }
    else if (i < 2 * WCHUNKS) { s = wk; d = owk; off = i - WCHUNKS; }
    else                      { s = wv; d = owv; off = i - 2 * WCHUNKS; }
    float4 a = s[2 * (size_t)off];
    float4 b = s[2 * (size_t)off + 1];
    uint4 o;
    o.x = h2u(__floats2half2_rn(a.x, a.y));
    o.y = h2u(__floats2half2_rn(a.z, a.w));
    o.z = h2u(__floats2half2_rn(b.x, b.y));
    o.w = h2u(__floats2half2_rn(b.z, b.w));
    d[off] = o;
}

// ======================= HMMA projection GEMM v6 (fused fp32 A load) =================
// 128 threads, CTA tile 128x128, warp tile 64x64 (2x2 warps), Kc=64.
// A: fp32 inputs loaded via LDG.128 register pipeline, converted to fp16, STS into
//    a single 16KB smem slot per iter (write -> sync -> LDSM -> sync).
// W: pre-converted fp16, 3-stage cp.async pipeline (3x16KB).
// smem 64KB, 2 CTAs/SM. grid (8, 514): y<256 k, y<512 v, else q.
#define PROJ_A16   0
#define PROJ_W0    16384
#define PROJ_WSTG  16384
#define PROJ_SMEM  (16384 + 3 * PROJ_WSTG)   // 64 KB

__global__ __launch_bounds__(128, 2) void proj_hmma(
    const float* __restrict__ Qf32, const float* __restrict__ Kf32, const float* __restrict__ Vf32,
    const __half* __restrict__ WQ, const __half* __restrict__ WK, const __half* __restrict__ WV,
    __half* __restrict__ QH, __half* __restrict__ KH, __half* __restrict__ VH)
{
    const float* A; const __half* W; __half* C;
    size_t rowbase;
    {
        const int y = blockIdx.y;
        if (y < 256)      { A = Kf32; W = WK; C = KH; rowbase = (size_t)y * 128; }
        else if (y < 512) { A = Vf32; W = WV; C = VH; rowbase = (size_t)(y - 256) * 128; }
        else              { A = Qf32; W = WQ; C = QH; rowbase = (size_t)(y - 512) * 128; }
    }

    extern __shared__ __align__(1024) char sm[];
    const uint32_t sb = smem_to_u32(sm);
    const int tid = threadIdx.x;
    const int lane = tid & 31;
    const int wid = tid >> 5;
    const int wm = wid & 1;
    const int wn = wid >> 1;

    const float* gA = A + rowbase * D_;
    const __half* gW = W + (size_t)blockIdx.x * 128 * D_;

    // shared loader geometry: 8 chunks/thread; chunk = 16B fp16 (= 32B fp32 for A)
    // chunk id c = tid + 128*p : row = c>>3 (0..127), j = c&7 (16B column chunk)
    uint32_t csw[8];   // swizzled smem offset of the 16B fp16 chunk
    uint32_t cgo[8];   // element offset within tile (row*D + j*8)
#pragma unroll
    for (int p = 0; p < 8; p++) {
        int c = tid + 128 * p;
        int row = c >> 3, j = c & 7;
        int off = row * 128 + j * 16;
        csw[p] = off ^ ((off >> 3) & 0x70);
        cgo[p] = row * D_ + j * 8;
    }

    const uint32_t xorv = (uint32_t)(lane & 7) << 4;
    const uint32_t a_h = (uint32_t)(lane >> 4) * 16;
    const uint32_t b_h = (uint32_t)((lane >> 3) & 1) * 16;
    uint32_t a_rowterm[4];
#pragma unroll
    for (int mb = 0; mb < 4; mb++)
        a_rowterm[mb] = (uint32_t)(wm * 64 + mb * 16 + (lane & 15)) * 128;
    uint32_t b_rowterm[4];
#pragma unroll
    for (int p = 0; p < 4; p++)
        b_rowterm[p] = (uint32_t)(wn * 64 + p * 16 + (lane & 7) + ((lane >> 4) << 3)) * 128;

    float acc[4][8][4];
#pragma unroll
    for (int mb = 0; mb < 4; mb++)
#pragma unroll
        for (int j = 0; j < 8; j++)
#pragma unroll
            for (int t = 0; t < 4; t++) acc[mb][j][t] = 0.f;

    // ---- A register pipeline: fp32 loads for the CURRENT iter live in f0/f1 ----
    float4 f0[8], f1[8];
    auto ldA = [&](int k0) {
#pragma unroll
        for (int p = 0; p < 8; p++) {
            const float* src = gA + cgo[p] + k0;
            f0[p] = *reinterpret_cast<const float4*>(src);
            f1[p] = *reinterpret_cast<const float4*>(src + 4);
        }
    };
    auto stsA = [&]() {
#pragma unroll
        for (int p = 0; p < 8; p++) {
            uint4 o;
            o.x = h2u(__floats2half2_rn(f0[p].x, f0[p].y));
            o.y = h2u(__floats2half2_rn(f0[p].z, f0[p].w));
            o.z = h2u(__floats2half2_rn(f1[p].x, f1[p].y));
            o.w = h2u(__floats2half2_rn(f1[p].z, f1[p].w));
            *reinterpret_cast<uint4*>(sm + PROJ_A16 + csw[p]) = o;
        }
    };
    auto issueW = [&](int it) {
        const uint32_t st = sb + PROJ_W0 + (uint32_t)(it % 3) * PROJ_WSTG;
        const uint32_t k0 = (uint32_t)it * 64;
#pragma unroll
        for (int p = 0; p < 8; p++)
            cp16(st + csw[p], gW + cgo[p] + k0);
        CP_COMMIT();
    };

    issueW(0); issueW(1); issueW(2);
    ldA(0);
#pragma unroll 1
    for (int it = 0; it < 16; it++) {
        stsA();                           // deposit current A (fp16) into the single slot
        if (it < 15) ldA((it + 1) * 64);  // refill A regs for next iter (latency covered)
        if (it <= 13)      { CP_WAIT(2); }
        else if (it == 14) { CP_WAIT(1); }
        else               { CP_WAIT(0); }
        __syncthreads();
        const uint32_t stW = sb + PROJ_W0 + (uint32_t)(it % 3) * PROJ_WSTG;
#pragma unroll
        for (int kk = 0; kk < 4; kk++) {
            const uint32_t k2 = (uint32_t)kk * 32;
            uint32_t Af[4][4];
#pragma unroll
            for (int mb = 0; mb < 4; mb++)
                LDSM4(Af[mb], sb + PROJ_A16 + a_rowterm[mb] + ((k2 + a_h) ^ xorv));
#pragma unroll
            for (int p = 0; p < 4; p++) {
                uint32_t Bf[4];
                LDSM4(Bf, stW + b_rowterm[p] + ((k2 + b_h) ^ xorv));
#pragma unroll
                for (int mb = 0; mb < 4; mb++) {
                    MMAF16(acc[mb][2 * p],     Af[mb], Bf[0], Bf[1]);
                    MMAF16(acc[mb][2 * p + 1], Af[mb], Bf[2], Bf[3]);
                }
            }
        }
        __syncthreads();
        if (it + 3 < 16) issueW(it + 3);
    }

    const int r = lane >> 2;
    const int cc = (lane & 3) * 2;
#pragma unroll
    for (int mb = 0; mb < 4; mb++) {
        const size_t row0 = rowbase + wm * 64 + mb * 16 + r;
#pragma unroll
        for (int j = 0; j < 8; j++) {
            const int col = blockIdx.x * 128 + wn * 64 + j * 8 + cc;
#pragma unroll
            for (int rr = 0; rr < 2; rr++) {
                const size_t idx = (row0 + 8 * rr) * D_ + col;
                *reinterpret_cast<__half2*>(&C[idx]) =
                    __floats2half2_rn(acc[mb][j][2 * rr], acc[mb][j][2 * rr + 1]);
            }
        }
    }
}

// ======================= fused flash attention v6 (unchanged from R15) ===============
#define FQ 0
#define FSTAGE0 8192
#define FSTG 32768
#define FSMEM (8192 + 2 * FSTG)
#define RED_STRIDE 66
#define SC_EXP 0.18033688011112042f   // 0.125 * log2(e)

__global__ __launch_bounds__(128, 3) void flash_attn(
    const __half* __restrict__ Q, const __half* __restrict__ K,
    const __half* __restrict__ V,
    float* __restrict__ Opart, float* __restrict__ Dpart)
{
    extern __shared__ __align__(1024) char sm[];
    const uint32_t sb = smem_to_u32(sm);
    const int tid = threadIdx.x;
    const int lane = tid & 31;
    const int wid = tid >> 5;
    const int wq = wid & 1;
    const int wk = wid >> 1;

    const int ns = blockIdx.x;
    const int bt = blockIdx.y;
    const int h  = blockIdx.z;
    const int key0 = ns * 1024;
    const int b0 = bt * 64;
    const int hcol = h * DH_;

    uint32_t lsw[8], lgo[8];
#pragma unroll
    for (int i = 0; i < 8; i++) {
        int e = tid + 128 * i;
        int row = e >> 3, c4 = e & 7;
        int off = row * 128 + c4 * 16;
        lsw[i] = off ^ ((off >> 3) & 0x70);
        lgo[i] = row * D_ + c4 * 8;
    }
    uint32_t qsw[4], qgo[4];
#pragma unroll
    for (int i = 0; i < 4; i++) {
        int e = tid + 128 * i;
        int row = e >> 3, c4 = e & 7;
        int off = row * 128 + c4 * 16;
        qsw[i] = off ^ ((off >> 3) & 0x70);
        qgo[i] = row * D_ + c4 * 8;
    }

#pragma unroll
    for (int i = 0; i < 4; i++)
        cp16(sb + FQ + qsw[i], Q + (size_t)b0 * D_ + hcol + qgo[i]);
    auto issueKV = [&](int sub) {
        const uint32_t st = sb + FSTAGE0 + (uint32_t)(sub & 1) * FSTG;
        const size_t gb = (size_t)(key0 + sub * 128) * D_ + hcol;
#pragma unroll
        for (int i = 0; i < 8; i++) {
            cp16(st + lsw[i],         K + gb + lgo[i]);
            cp16(st + 16384 + lsw[i], V + gb + lgo[i]);
        }
        CP_COMMIT();
    };
    issueKV(0); issueKV(1);

    const uint32_t swz = (uint32_t)(lane & 7) << 4;
    const uint32_t a_h = (uint32_t)(lane >> 4) * 16;
    uint32_t a_rowterm[2];
#pragma unroll
    for (int mb = 0; mb < 2; mb++)
        a_rowterm[mb] = (uint32_t)(wq * 32 + mb * 16 + (lane & 15)) * 128;
    const uint32_t k_h = (uint32_t)((lane >> 3) & 1) * 16;
    uint32_t k_rowbase[4];
#pragma unroll
    for (int jj = 0; jj < 4; jj++)
        k_rowbase[jj] = (uint32_t)(wk * 64 + jj * 16 + (lane & 7) + ((lane >> 4) << 3)) * 128;
    const uint32_t v_h = (uint32_t)(lane >> 4) * 16;
    uint32_t v_rowbase[4];
#pragma unroll
    for (int s2 = 0; s2 < 4; s2++)
        v_rowbase[s2] = (uint32_t)(wk * 64 + s2 * 16 + (lane & 7) + (((lane >> 3) & 1) << 3)) * 128;

    float oacc[2][8][4];
#pragma unroll
    for (int mb = 0; mb < 2; mb++)
#pragma unroll
        for (int j = 0; j < 8; j++)
#pragma unroll
            for (int t = 0; t < 4; t++) oacc[mb][j][t] = 0.f;
    float rs[2][2] = {{0.f, 0.f}, {0.f, 0.f}};

#pragma unroll 1
    for (int sub = 0; sub < 8; sub++) {
        if (sub < 7) { CP_WAIT(1); } else { CP_WAIT(0); }
        __syncthreads();
        const uint32_t st = sb + FSTAGE0 + (uint32_t)(sub & 1) * FSTG;

#pragma unroll
        for (int half = 0; half < 2; half++) {
            float sacc[2][4][4];
#pragma unroll
            for (int mb = 0; mb < 2; mb++)
#pragma unroll
                for (int j = 0; j < 4; j++)
#pragma unroll
                    for (int t = 0; t < 4; t++) sacc[mb][j][t] = 0.f;

#pragma unroll
            for (int s = 0; s < 4; s++) {
                uint32_t Qf[2][4];
                const uint32_t colq = (s * 32 + a_h) ^ swz;
#pragma unroll
                for (int mb = 0; mb < 2; mb++)
                    LDSM4(Qf[mb], sb + FQ + a_rowterm[mb] + colq);
                const uint32_t colb = (s * 32 + k_h) ^ swz;
#pragma unroll
                for (int jj = 0; jj < 2; jj++) {
                    uint32_t Kf[4];
                    LDSM4(Kf, st + k_rowbase[half * 2 + jj] + colb);
#pragma unroll
                    for (int mb = 0; mb < 2; mb++) {
                        MMAF16(sacc[mb][2 * jj],     Qf[mb], Kf[0], Kf[1]);
                        MMAF16(sacc[mb][2 * jj + 1], Qf[mb], Kf[2], Kf[3]);
                    }
                }
            }

#pragma unroll
            for (int g2 = 0; g2 < 2; g2++) {
                const int s2 = half * 2 + g2;
                uint32_t Pf[2][4];
#pragma unroll
                for (int mb = 0; mb < 2; mb++) {
                    float e0 = exp2f(sacc[mb][2 * g2][0] * SC_EXP);
                    float e1 = exp2f(sacc[mb][2 * g2][1] * SC_EXP);
                    float e2 = exp2f(sacc[mb][2 * g2][2] * SC_EXP);
                    float e3 = exp2f(sacc[mb][2 * g2][3] * SC_EXP);
                    float f0 = exp2f(sacc[mb][2 * g2 + 1][0] * SC_EXP);
                    float f1 = exp2f(sacc[mb][2 * g2 + 1][1] * SC_EXP);
                    float f2 = exp2f(sacc[mb][2 * g2 + 1][2] * SC_EXP);
                    float f3 = exp2f(sacc[mb][2 * g2 + 1][3] * SC_EXP);
                    rs[mb][0] += (e0 + e1) + (f0 + f1);
                    rs[mb][1] += (e2 + e3) + (f2 + f3);
                    Pf[mb][0] = h2u(__floats2half2_rn(e0, e1));
                    Pf[mb][1] = h2u(__floats2half2_rn(e2, e3));
                    Pf[mb][2] = h2u(__floats2half2_rn(f0, f1));
                    Pf[mb][3] = h2u(__floats2half2_rn(f2, f3));
                }
#pragma unroll
                for (int p = 0; p < 4; p++) {
                    uint32_t Vf[4];
                    LDSM4T(Vf, st + 16384 + v_rowbase[s2] + ((p * 32 + v_h) ^ swz));
#pragma unroll
                    for (int mb = 0; mb < 2; mb++) {
                        MMAF16(oacc[mb][2 * p],     Pf[mb], Vf[0], Vf[1]);
                        MMAF16(oacc[mb][2 * p + 1], Pf[mb], Vf[2], Vf[3]);
                    }
                }
            }
        }
        __syncthreads();
        if (sub + 2 < 8) issueKV(sub + 2);
    }

    const int g = lane >> 2;
    const int t = lane & 3;
#pragma unroll
    for (int mb = 0; mb < 2; mb++)
#pragma unroll
        for (int i = 0; i < 2; i++) {
            rs[mb][i] += __shfl_xor_sync(0xffffffffu, rs[mb][i], 1);
            rs[mb][i] += __shfl_xor_sync(0xffffffffu, rs[mb][i], 2);
        }

    float* sred = reinterpret_cast<float*>(sm + FSTAGE0);
    float* srs  = reinterpret_cast<float*>(sm + FSTAGE0 + 64 * RED_STRIDE * 4);
    if (wk == 1) {
#pragma unroll
        for (int mb = 0; mb < 2; mb++) {
            const int r0 = wq * 32 + mb * 16 + g;
#pragma unroll
            for (int j = 0; j < 8; j++) {
                const int col = j * 8 + 2 * t;
                sred[r0 * RED_STRIDE + col]           = oacc[mb][j][0];
                sred[r0 * RED_STRIDE + col + 1]       = oacc[mb][j][1];
                sred[(r0 + 8) * RED_STRIDE + col]     = oacc[mb][j][2];
                sred[(r0 + 8) * RED_STRIDE + col + 1] = oacc[mb][j][3];
            }
            if (t == 0) { srs[r0] = rs[mb][0]; srs[r0 + 8] = rs[mb][1]; }
        }
    }
    __syncthreads();
    if (wk == 0) {
        const int slice = (h * 4 + bt) * NSPLIT + ns;
        float* ob = Opart + (size_t)slice * 64 * DH_;
#pragma unroll
        for (int mb = 0; mb < 2; mb++) {
            const int r0 = wq * 32 + mb * 16 + g;
#pragma unroll
            for (int j = 0; j < 8; j++) {
                const int col = j * 8 + 2 * t;
                *reinterpret_cast<float2*>(&ob[(size_t)r0 * DH_ + col]) = make_float2(
                    oacc[mb][j][0] + sred[r0 * RED_STRIDE + col],
                    oacc[mb][j][1] + sred[r0 * RED_STRIDE + col + 1]);
                *reinterpret_cast<float2*>(&ob[(size_t)(r0 + 8) * DH_ + col]) = make_float2(
                    oacc[mb][j][2] + sred[(r0 + 8) * RED_STRIDE + col],
                    oacc[mb][j][3] + sred[(r0 + 8) * RED_STRIDE + col + 1]);
            }
            if (t == 0) {
                Dpart[(size_t)slice * 64 + r0]     = rs[mb][0] + srs[r0];
                Dpart[(size_t)slice * 64 + r0 + 8] = rs[mb][1] + srs[r0 + 8];
            }
        }
    }
}

// ======================= final reduce =======================
__global__ __launch_bounds__(256) void flash_reduce(const float* __restrict__ Opart,
                                                    const float* __restrict__ Dpart,
                                                    float* __restrict__ out)
{
    const int idx = blockIdx.x * 256 + threadIdx.x;
    const int b  = idx >> 10;
    const int col = idx & 1023;
    const int h  = col >> 6;
    const int c  = col & 63;
    const int bt = b >> 6;
    const int r  = b & 63;
    const size_t base = (size_t)(h * 4 + bt) * NSPLIT;
    float o = 0.f, d = 0.f;
#pragma unroll
    for (int ns = 0; ns < NSPLIT; ns++) {
        o += Opart[(base + ns) * 64 * DH_ + (size_t)r * DH_ + c];
        d += Dpart[(base + ns) * 64 + r];
    }
    out[idx] = o / d;
}

// ---------------- launch ----------------
extern "C" void kernel_launch(void* const* d_in, const int* in_sizes, int n_in,
                              void* d_out, int out_size)
{
    const float* q  = (const float*)d_in[0];
    const float* k  = (const float*)d_in[1];
    const float* v  = (const float*)d_in[2];
    const float* Wq = (const float*)d_in[3];
    const float* Wk = (const float*)d_in[4];
    const float* Wv = (const float*)d_in[5];
    float* out = (float*)d_out;

    __half *wq16, *wk16, *wv16, *qh16, *kh16, *vh16;
    cudaGetSymbolAddress((void**)&wq16, g_wq16);
    cudaGetSymbolAddress((void**)&wk16, g_wk16);
    cudaGetSymbolAddress((void**)&wv16, g_wv16);
    cudaGetSymbolAddress((void**)&qh16, g_qh16);
    cudaGetSymbolAddress((void**)&kh16, g_kh16);
    cudaGetSymbolAddress((void**)&vh16, g_vh16);

    float *op, *dp;
    cudaGetSymbolAddress((void**)&op, g_opart);
    cudaGetSymbolAddress((void**)&dp, g_dpart);

    cudaFuncSetAttribute(proj_hmma, cudaFuncAttributeMaxDynamicSharedMemorySize, PROJ_SMEM);
    cudaFuncSetAttribute(flash_attn, cudaFuncAttributeMaxDynamicSharedMemorySize, FSMEM);

    // 0) W-only fp32 -> fp16 convert (12 MB)
    cvt_w<<<3 * WCHUNKS / 256, 256>>>(
        (const float4*)Wq, (const float4*)Wk, (const float4*)Wv,
        (uint4*)wq16, (uint4*)wk16, (uint4*)wv16);

    // 1) projections (A converted in-kernel from fp32)
    proj_hmma<<<dim3(D_ / 128, 2 * (N_ / 128) + B_ / 128), 128, PROJ_SMEM>>>(
        q, k, v, wq16, wk16, wv16, qh16, kh16, vh16);

    // 2) fused flash attention -> partials
    flash_attn<<<dim3(NSPLIT, 4, H_), 128, FSMEM>>>(qh16, kh16, vh16, op, dp);

    // 3) combine partials
    flash_reduce<<<(B_ * D_) / 256, 256>>>(op, dp, out);
}

// round 17
// speedup vs baseline: 1.1636x; 1.1636x over previous
#include <cuda_runtime.h>
#include <cuda_fp16.h>
#include <cstdint>

#define B_  256
#define N_  32768
#define D_  1024
#define H_  16
#define DH_ 64

// ---------------- scratch ----------------
__device__ __align__(16) __half g_q16[(size_t)B_ * D_];
__device__ __align__(16) __half g_k16[(size_t)N_ * D_];
__device__ __align__(16) __half g_v16[(size_t)N_ * D_];
__device__ __align__(16) __half g_wq16[(size_t)D_ * D_];
__device__ __align__(16) __half g_wk16[(size_t)D_ * D_];
__device__ __align__(16) __half g_wv16[(size_t)D_ * D_];
__device__ __align__(16) __half g_qh16[(size_t)B_ * D_];
__device__ __align__(16) __half g_kh16[(size_t)N_ * D_];
__device__ __align__(16) __half g_vh16[(size_t)N_ * D_];
#define NSPLIT 16
#define KEYS_PER_CTA 2048
#define NSUB 16
__device__ __align__(16) float g_opart[(size_t)H_ * 4 * NSPLIT * 64 * DH_];  // 16.8 MB
__device__ __align__(16) float g_dpart[(size_t)H_ * 4 * NSPLIT * 64];

// ======================= helpers =======================
__device__ __forceinline__ uint32_t smem_to_u32(const void* p) {
    uint32_t a;
    asm("{ .reg .u64 t; cvta.to.shared.u64 t, %1; cvt.u32.u64 %0, t; }" : "=r"(a) : "l"(p));
    return a;
}
__device__ __forceinline__ void cp16(uint32_t s, const void* g) {
    asm volatile("cp.async.cg.shared.global [%0], [%1], 16;" :: "r"(s), "l"(g) : "memory");
}
#define CP_COMMIT() asm volatile("cp.async.commit_group;" ::: "memory")
#define CP_WAIT(n)  asm volatile("cp.async.wait_group %0;" :: "n"(n) : "memory")

#define LDSM4(r, a) \
    asm volatile("ldmatrix.sync.aligned.m8n8.x4.shared.b16 {%0,%1,%2,%3}, [%4];" \
        : "=r"((r)[0]), "=r"((r)[1]), "=r"((r)[2]), "=r"((r)[3]) : "r"(a))
#define LDSM4T(r, a) \
    asm volatile("ldmatrix.sync.aligned.m8n8.x4.trans.shared.b16 {%0,%1,%2,%3}, [%4];" \
        : "=r"((r)[0]), "=r"((r)[1]), "=r"((r)[2]), "=r"((r)[3]) : "r"(a))

#define MMAF16(c, a, b0, b1) \
    asm volatile("mma.sync.aligned.m16n8k16.row.col.f32.f16.f16.f32 " \
        "{%0,%1,%2,%3}, {%4,%5,%6,%7}, {%8,%9}, {%0,%1,%2,%3};" \
        : "+f"((c)[0]), "+f"((c)[1]), "+f"((c)[2]), "+f"((c)[3]) \
        : "r"((a)[0]), "r"((a)[1]), "r"((a)[2]), "r"((a)[3]), "r"(b0), "r"(b1))

__device__ __forceinline__ uint32_t h2u(__half2 h) { return *reinterpret_cast<uint32_t*>(&h); }

// ======================= fused fp32 -> fp16 convert =======================
#define CV_Q  32768u
#define CV_K  4194304u
#define CV_W  131072u
#define CC1 (CV_Q)
#define CC2 (CC1 + CV_K)
#define CC3 (CC2 + CV_K)
#define CC4 (CC3 + CV_W)
#define CC5 (CC4 + CV_W)
#define CC6 (CC5 + CV_W)

__global__ __launch_bounds__(256) void cvt_all(
    const float4* __restrict__ q, const float4* __restrict__ k, const float4* __restrict__ v,
    const float4* __restrict__ wq, const float4* __restrict__ wk, const float4* __restrict__ wv,
    uint4* __restrict__ oq, uint4* __restrict__ ok, uint4* __restrict__ ov,
    uint4* __restrict__ owq, uint4* __restrict__ owk, uint4* __restrict__ owv)
{
    uint32_t i = blockIdx.x * 256 + threadIdx.x;
    const uint32_t stride = gridDim.x * 256;
#pragma unroll 1
    for (; i < CC6; i += stride) {
        const float4* s; uint4* d; uint32_t off;
        if      (i < CC1) { s = q;  d = oq;  off = i; }
        else if (i < CC2) { s = k;  d = ok;  off = i - CC1; }
        else if (i < CC3) { s = v;  d = ov;  off = i - CC2; }
        else if (i < CC4) { s = wq; d = owq; off = i - CC3; }
        else if (i < CC5) { s = wk; d = owk; off = i - CC4; }
        else              { s = wv; d = owv; off = i - CC5; }
        float4 a = s[2 * (size_t)off];
        float4 b = s[2 * (size_t)off + 1];
        uint4 o;
        o.x = h2u(__floats2half2_rn(a.x, a.y));
        o.y = h2u(__floats2half2_rn(a.z, a.w));
        o.z = h2u(__floats2half2_rn(b.x, b.y));
        o.w = h2u(__floats2half2_rn(b.z, b.w));
        d[off] = o;
    }
}

// ======================= HMMA projection GEMM v5 (R10/R15 proven) =======================
#define PROJ_STG 32768
#define PROJ_SMEM (3 * PROJ_STG)

__global__ __launch_bounds__(128, 2) void proj_hmma(
    const __half* __restrict__ Q16, const __half* __restrict__ K16, const __half* __restrict__ V16,
    const __half* __restrict__ WQ, const __half* __restrict__ WK, const __half* __restrict__ WV,
    __half* __restrict__ QH, __half* __restrict__ KH, __half* __restrict__ VH)
{
    const __half* A; const __half* W; __half* C;
    size_t rowbase;
    {
        const int y = blockIdx.y;
        if (y < 256)      { A = K16; W = WK; C = KH; rowbase = (size_t)y * 128; }
        else if (y < 512) { A = V16; W = WV; C = VH; rowbase = (size_t)(y - 256) * 128; }
        else              { A = Q16; W = WQ; C = QH; rowbase = (size_t)(y - 512) * 128; }
    }

    extern __shared__ __align__(1024) char sm[];
    const uint32_t sb = smem_to_u32(sm);
    const int tid = threadIdx.x;
    const int lane = tid & 31;
    const int wid = tid >> 5;
    const int wm = wid & 1;
    const int wn = wid >> 1;

    const __half* gA = A + rowbase * D_;
    const __half* gW = W + (size_t)blockIdx.x * 128 * D_;

    uint32_t sOf[8], gOf[8];
#pragma unroll
    for (int i = 0; i < 8; i++) {
        int e = tid + 128 * i;
        int row = e >> 3, c4 = e & 7;
        int off = row * 128 + c4 * 16;
        sOf[i] = off ^ ((off >> 3) & 0x70);
        gOf[i] = row * D_ + c4 * 8;
    }

    const uint32_t xorv = (uint32_t)(lane & 7) << 4;
    const uint32_t a_h = (uint32_t)(lane >> 4) * 16;
    const uint32_t b_h = (uint32_t)((lane >> 3) & 1) * 16;
    uint32_t a_rowterm[4];
#pragma unroll
    for (int mb = 0; mb < 4; mb++)
        a_rowterm[mb] = (uint32_t)(wm * 64 + mb * 16 + (lane & 15)) * 128;
    uint32_t b_rowterm[4];
#pragma unroll
    for (int p = 0; p < 4; p++)
        b_rowterm[p] = (uint32_t)(wn * 64 + p * 16 + (lane & 7) + ((lane >> 4) << 3)) * 128;

    float acc[4][8][4];
#pragma unroll
    for (int mb = 0; mb < 4; mb++)
#pragma unroll
        for (int j = 0; j < 8; j++)
#pragma unroll
            for (int t = 0; t < 4; t++) acc[mb][j][t] = 0.f;

    auto issue = [&](int it) {
        const uint32_t st = sb + (uint32_t)(it % 3) * PROJ_STG;
        const uint32_t k0 = (uint32_t)it * 64;
#pragma unroll
        for (int i = 0; i < 8; i++) {
            cp16(st + sOf[i],         gA + gOf[i] + k0);
            cp16(st + 16384 + sOf[i], gW + gOf[i] + k0);
        }
        CP_COMMIT();
    };

    issue(0); issue(1); issue(2);
#pragma unroll 1
    for (int it = 0; it < 16; it++) {
        if (it <= 13)      { CP_WAIT(2); }
        else if (it == 14) { CP_WAIT(1); }
        else               { CP_WAIT(0); }
        __syncthreads();
        const uint32_t st = sb + (uint32_t)(it % 3) * PROJ_STG;
#pragma unroll
        for (int kk = 0; kk < 4; kk++) {
            const uint32_t k2 = (uint32_t)kk * 32;
            uint32_t Af[4][4];
#pragma unroll
            for (int mb = 0; mb < 4; mb++)
                LDSM4(Af[mb], st + a_rowterm[mb] + ((k2 + a_h) ^ xorv));
#pragma unroll
            for (int p = 0; p < 4; p++) {
                uint32_t Bf[4];
                LDSM4(Bf, st + 16384 + b_rowterm[p] + ((k2 + b_h) ^ xorv));
#pragma unroll
                for (int mb = 0; mb < 4; mb++) {
                    MMAF16(acc[mb][2 * p],     Af[mb], Bf[0], Bf[1]);
                    MMAF16(acc[mb][2 * p + 1], Af[mb], Bf[2], Bf[3]);
                }
            }
        }
        __syncthreads();
        if (it + 3 < 16) issue(it + 3);
    }

    const int r = lane >> 2;
    const int cc = (lane & 3) * 2;
#pragma unroll
    for (int mb = 0; mb < 4; mb++) {
        const size_t row0 = rowbase + wm * 64 + mb * 16 + r;
#pragma unroll
        for (int j = 0; j < 8; j++) {
            const int col = blockIdx.x * 128 + wn * 64 + j * 8 + cc;
#pragma unroll
            for (int rr = 0; rr < 2; rr++) {
                const size_t idx = (row0 + 8 * rr) * D_ + col;
                *reinterpret_cast<__half2*>(&C[idx]) =
                    __floats2half2_rn(acc[mb][j][2 * rr], acc[mb][j][2 * rr + 1]);
            }
        }
    }
}

// ======================= fused flash attention v7 (R15 core, NSPLIT=16) ===============
// grid (NSPLIT, 4, H). CTA: 64 q-rows x dh64, 2048 keys in 128-key sub-chunks,
// 2-stage pipeline, 3 CTAs/SM. 4 warps = 2 wq (32 q-rows) x 2 wk (64 keys).
#define FQ 0
#define FSTAGE0 8192
#define FSTG 32768
#define FSMEM (8192 + 2 * FSTG)
#define RED_STRIDE 66
#define SC_EXP 0.18033688011112042f   // 0.125 * log2(e)

__global__ __launch_bounds__(128, 3) void flash_attn(
    const __half* __restrict__ Q, const __half* __restrict__ K,
    const __half* __restrict__ V,
    float* __restrict__ Opart, float* __restrict__ Dpart)
{
    extern __shared__ __align__(1024) char sm[];
    const uint32_t sb = smem_to_u32(sm);
    const int tid = threadIdx.x;
    const int lane = tid & 31;
    const int wid = tid >> 5;
    const int wq = wid & 1;
    const int wk = wid >> 1;

    const int ns = blockIdx.x;
    const int bt = blockIdx.y;
    const int h  = blockIdx.z;
    const int key0 = ns * KEYS_PER_CTA;
    const int b0 = bt * 64;
    const int hcol = h * DH_;

    uint32_t lsw[8], lgo[8];
#pragma unroll
    for (int i = 0; i < 8; i++) {
        int e = tid + 128 * i;
        int row = e >> 3, c4 = e & 7;
        int off = row * 128 + c4 * 16;
        lsw[i] = off ^ ((off >> 3) & 0x70);
        lgo[i] = row * D_ + c4 * 8;
    }
    uint32_t qsw[4], qgo[4];
#pragma unroll
    for (int i = 0; i < 4; i++) {
        int e = tid + 128 * i;
        int row = e >> 3, c4 = e & 7;
        int off = row * 128 + c4 * 16;
        qsw[i] = off ^ ((off >> 3) & 0x70);
        qgo[i] = row * D_ + c4 * 8;
    }

#pragma unroll
    for (int i = 0; i < 4; i++)
        cp16(sb + FQ + qsw[i], Q + (size_t)b0 * D_ + hcol + qgo[i]);
    auto issueKV = [&](int sub) {
        const uint32_t st = sb + FSTAGE0 + (uint32_t)(sub & 1) * FSTG;
        const size_t gb = (size_t)(key0 + sub * 128) * D_ + hcol;
#pragma unroll
        for (int i = 0; i < 8; i++) {
            cp16(st + lsw[i],         K + gb + lgo[i]);
            cp16(st + 16384 + lsw[i], V + gb + lgo[i]);
        }
        CP_COMMIT();
    };
    issueKV(0); issueKV(1);

    const uint32_t swz = (uint32_t)(lane & 7) << 4;
    const uint32_t a_h = (uint32_t)(lane >> 4) * 16;
    uint32_t a_rowterm[2];
#pragma unroll
    for (int mb = 0; mb < 2; mb++)
        a_rowterm[mb] = (uint32_t)(wq * 32 + mb * 16 + (lane & 15)) * 128;
    const uint32_t k_h = (uint32_t)((lane >> 3) & 1) * 16;
    uint32_t k_rowbase[4];
#pragma unroll
    for (int jj = 0; jj < 4; jj++)
        k_rowbase[jj] = (uint32_t)(wk * 64 + jj * 16 + (lane & 7) + ((lane >> 4) << 3)) * 128;
    const uint32_t v_h = (uint32_t)(lane >> 4) * 16;
    uint32_t v_rowbase[4];
#pragma unroll
    for (int s2 = 0; s2 < 4; s2++)
        v_rowbase[s2] = (uint32_t)(wk * 64 + s2 * 16 + (lane & 7) + (((lane >> 3) & 1) << 3)) * 128;

    float oacc[2][8][4];
#pragma unroll
    for (int mb = 0; mb < 2; mb++)
#pragma unroll
        for (int j = 0; j < 8; j++)
#pragma unroll
            for (int t = 0; t < 4; t++) oacc[mb][j][t] = 0.f;
    float rs[2][2] = {{0.f, 0.f}, {0.f, 0.f}};

#pragma unroll 1
    for (int sub = 0; sub < NSUB; sub++) {
        if (sub < NSUB - 1) { CP_WAIT(1); } else { CP_WAIT(0); }
        __syncthreads();
        const uint32_t st = sb + FSTAGE0 + (uint32_t)(sub & 1) * FSTG;

        // two 32-key halves: sacc live range = 32 regs (no spills)
#pragma unroll
        for (int half = 0; half < 2; half++) {
            float sacc[2][4][4];
#pragma unroll
            for (int mb = 0; mb < 2; mb++)
#pragma unroll
                for (int j = 0; j < 4; j++)
#pragma unroll
                    for (int t = 0; t < 4; t++) sacc[mb][j][t] = 0.f;

#pragma unroll
            for (int s = 0; s < 4; s++) {
                uint32_t Qf[2][4];
                const uint32_t colq = (s * 32 + a_h) ^ swz;
#pragma unroll
                for (int mb = 0; mb < 2; mb++)
                    LDSM4(Qf[mb], sb + FQ + a_rowterm[mb] + colq);
                const uint32_t colb = (s * 32 + k_h) ^ swz;
#pragma unroll
                for (int jj = 0; jj < 2; jj++) {
                    uint32_t Kf[4];
                    LDSM4(Kf, st + k_rowbase[half * 2 + jj] + colb);
#pragma unroll
                    for (int mb = 0; mb < 2; mb++) {
                        MMAF16(sacc[mb][2 * jj],     Qf[mb], Kf[0], Kf[1]);
                        MMAF16(sacc[mb][2 * jj + 1], Qf[mb], Kf[2], Kf[3]);
                    }
                }
            }

#pragma unroll
            for (int g2 = 0; g2 < 2; g2++) {
                const int s2 = half * 2 + g2;
                uint32_t Pf[2][4];
#pragma unroll
                for (int mb = 0; mb < 2; mb++) {
                    float e0 = exp2f(sacc[mb][2 * g2][0] * SC_EXP);
                    float e1 = exp2f(sacc[mb][2 * g2][1] * SC_EXP);
                    float e2 = exp2f(sacc[mb][2 * g2][2] * SC_EXP);
                    float e3 = exp2f(sacc[mb][2 * g2][3] * SC_EXP);
                    float f0 = exp2f(sacc[mb][2 * g2 + 1][0] * SC_EXP);
                    float f1 = exp2f(sacc[mb][2 * g2 + 1][1] * SC_EXP);
                    float f2 = exp2f(sacc[mb][2 * g2 + 1][2] * SC_EXP);
                    float f3 = exp2f(sacc[mb][2 * g2 + 1][3] * SC_EXP);
                    rs[mb][0] += (e0 + e1) + (f0 + f1);
                    rs[mb][1] += (e2 + e3) + (f2 + f3);
                    Pf[mb][0] = h2u(__floats2half2_rn(e0, e1));
                    Pf[mb][1] = h2u(__floats2half2_rn(e2, e3));
                    Pf[mb][2] = h2u(__floats2half2_rn(f0, f1));
                    Pf[mb][3] = h2u(__floats2half2_rn(f2, f3));
                }
#pragma unroll
                for (int p = 0; p < 4; p++) {
                    uint32_t Vf[4];
                    LDSM4T(Vf, st + 16384 + v_rowbase[s2] + ((p * 32 + v_h) ^ swz));
#pragma unroll
                    for (int mb = 0; mb < 2; mb++) {
                        MMAF16(oacc[mb][2 * p],     Pf[mb], Vf[0], Vf[1]);
                        MMAF16(oacc[mb][2 * p + 1], Pf[mb], Vf[2], Vf[3]);
                    }
                }
            }
        }
        __syncthreads();
        if (sub + 2 < NSUB) issueKV(sub + 2);
    }

    // ---- epilogue: combine wk halves in smem ----
    const int g = lane >> 2;
    const int t = lane & 3;
#pragma unroll
    for (int mb = 0; mb < 2; mb++)
#pragma unroll
        for (int i = 0; i < 2; i++) {
            rs[mb][i] += __shfl_xor_sync(0xffffffffu, rs[mb][i], 1);
            rs[mb][i] += __shfl_xor_sync(0xffffffffu, rs[mb][i], 2);
        }

    float* sred = reinterpret_cast<float*>(sm + FSTAGE0);
    float* srs  = reinterpret_cast<float*>(sm + FSTAGE0 + 64 * RED_STRIDE * 4);
    if (wk == 1) {
#pragma unroll
        for (int mb = 0; mb < 2; mb++) {
            const int r0 = wq * 32 + mb * 16 + g;
#pragma unroll
            for (int j = 0; j < 8; j++) {
                const int col = j * 8 + 2 * t;
                sred[r0 * RED_STRIDE + col]           = oacc[mb][j][0];
                sred[r0 * RED_STRIDE + col + 1]       = oacc[mb][j][1];
                sred[(r0 + 8) * RED_STRIDE + col]     = oacc[mb][j][2];
                sred[(r0 + 8) * RED_STRIDE + col + 1] = oacc[mb][j][3];
            }
            if (t == 0) { srs[r0] = rs[mb][0]; srs[r0 + 8] = rs[mb][1]; }
        }
    }
    __syncthreads();
    if (wk == 0) {
        const int slice = (h * 4 + bt) * NSPLIT + ns;
        float* ob = Opart + (size_t)slice * 64 * DH_;
#pragma unroll
        for (int mb = 0; mb < 2; mb++) {
            const int r0 = wq * 32 + mb * 16 + g;
#pragma unroll
            for (int j = 0; j < 8; j++) {
                const int col = j * 8 + 2 * t;
                *reinterpret_cast<float2*>(&ob[(size_t)r0 * DH_ + col]) = make_float2(
                    oacc[mb][j][0] + sred[r0 * RED_STRIDE + col],
                    oacc[mb][j][1] + sred[r0 * RED_STRIDE + col + 1]);
                *reinterpret_cast<float2*>(&ob[(size_t)(r0 + 8) * DH_ + col]) = make_float2(
                    oacc[mb][j][2] + sred[(r0 + 8) * RED_STRIDE + col],
                    oacc[mb][j][3] + sred[(r0 + 8) * RED_STRIDE + col + 1]);
            }
            if (t == 0) {
                Dpart[(size_t)slice * 64 + r0]     = rs[mb][0] + srs[r0];
                Dpart[(size_t)slice * 64 + r0 + 8] = rs[mb][1] + srs[r0 + 8];
            }
        }
    }
}

// ======================= final reduce =======================
__global__ __launch_bounds__(256) void flash_reduce(const float* __restrict__ Opart,
                                                    const float* __restrict__ Dpart,
                                                    float* __restrict__ out)
{
    const int idx = blockIdx.x * 256 + threadIdx.x;
    const int b  = idx >> 10;
    const int col = idx & 1023;
    const int h  = col >> 6;
    const int c  = col & 63;
    const int bt = b >> 6;
    const int r  = b & 63;
    const size_t base = (size_t)(h * 4 + bt) * NSPLIT;
    float o = 0.f, d = 0.f;
#pragma unroll
    for (int ns = 0; ns < NSPLIT; ns++) {
        o += Opart[(base + ns) * 64 * DH_ + (size_t)r * DH_ + c];
        d += Dpart[(base + ns) * 64 + r];
    }
    out[idx] = o / d;
}

// ---------------- launch ----------------
extern "C" void kernel_launch(void* const* d_in, const int* in_sizes, int n_in,
                              void* d_out, int out_size)
{
    const float* q  = (const float*)d_in[0];
    const float* k  = (const float*)d_in[1];
    const float* v  = (const float*)d_in[2];
    const float* Wq = (const float*)d_in[3];
    const float* Wk = (const float*)d_in[4];
    const float* Wv = (const float*)d_in[5];
    float* out = (float*)d_out;

    __half *q16, *k16, *v16, *wq16, *wk16, *wv16, *qh16, *kh16, *vh16;
    cudaGetSymbolAddress((void**)&q16,  g_q16);
    cudaGetSymbolAddress((void**)&k16,  g_k16);
    cudaGetSymbolAddress((void**)&v16,  g_v16);
    cudaGetSymbolAddress((void**)&wq16, g_wq16);
    cudaGetSymbolAddress((void**)&wk16, g_wk16);
    cudaGetSymbolAddress((void**)&wv16, g_wv16);
    cudaGetSymbolAddress((void**)&qh16, g_qh16);
    cudaGetSymbolAddress((void**)&kh16, g_kh16);
    cudaGetSymbolAddress((void**)&vh16, g_vh16);

    float *op, *dp;
    cudaGetSymbolAddress((void**)&op, g_opart);
    cudaGetSymbolAddress((void**)&dp, g_dpart);

    cudaFuncSetAttribute(proj_hmma, cudaFuncAttributeMaxDynamicSharedMemorySize, PROJ_SMEM);
    cudaFuncSetAttribute(flash_attn, cudaFuncAttributeMaxDynamicSharedMemorySize, FSMEM);

    // 0) fused fp32 -> fp16 convert
    cvt_all<<<4096, 256>>>(
        (const float4*)q, (const float4*)k, (const float4*)v,
        (const float4*)Wq, (const float4*)Wk, (const float4*)Wv,
        (uint4*)q16, (uint4*)k16, (uint4*)v16,
        (uint4*)wq16, (uint4*)wk16, (uint4*)wv16);

    // 1) projections
    proj_hmma<<<dim3(D_ / 128, 2 * (N_ / 128) + B_ / 128), 128, PROJ_SMEM>>>(
        q16, k16, v16, wq16, wk16, wv16, qh16, kh16, vh16);

    // 2) fused flash attention -> partials (3 CTAs/SM, 2048 keys/CTA)
    flash_attn<<<dim3(NSPLIT, 4, H_), 128, FSMEM>>>(qh16, kh16, vh16, op, dp);

    // 3) combine partials
    flash_reduce<<<(B_ * D_) / 256, 256>>>(op, dp, out);
}